// round 2
// baseline (speedup 1.0000x reference)
#include <cuda_runtime.h>
#include <cuda_bf16.h>

// Problem constants (fixed by setup_inputs)
#define HEIGHT 256
#define WIDTH  256
#define NBATCH 128
#define NK     4
#define NPAR   28          // 7*K params per mixture
#define PIX    (HEIGHT * WIDTH)
#define PIX_PER_THREAD 4
#define THREADS 256
#define PIX_PER_BLOCK (THREADS * PIX_PER_THREAD)   // 1024

__device__ __forceinline__ float fast_ex2(float x) {
    float r;
    asm("ex2.approx.f32 %0, %1;" : "=f"(r) : "f"(x));
    return r;
}

__global__ __launch_bounds__(THREADS, 8)
void moe_gauss_kernel(const float* __restrict__ params, float* __restrict__ out) {
    const int b    = blockIdx.y;                    // mixture index
    const int tid  = threadIdx.x;
    const int p0   = blockIdx.x * PIX_PER_BLOCK + tid * PIX_PER_THREAD; // first pixel

    // All 4 pixels of this thread lie in the same output row i (p0 % 256 in {0,4,...,252})
    const int i  = p0 >> 8;        // row
    const int j0 = p0 & 255;       // first col

    const float* __restrict__ p = params + b * NPAR;

    // param layout per mixture: mu_x[0:4], mu_y[4:8], w[8:12],
    // Sig[12:28] = K x (2x2 row-major), tril => s01 ignored.
    float mux[NK], muy[NK], wk[NK], A[NK], C[NK], D[NK];
#pragma unroll
    for (int k = 0; k < NK; k++) {
        mux[k] = __ldg(p + k);
        muy[k] = __ldg(p + NK + k);
        wk[k]  = __ldg(p + 2 * NK + k);
        A[k]   = __ldg(p + 3 * NK + 4 * k + 0);   // s00
        C[k]   = __ldg(p + 3 * NK + 4 * k + 2);   // s10
        D[k]   = __ldg(p + 3 * NK + 4 * k + 3);   // s11
    }

    const float inv255 = 1.0f / 255.0f;
    const float x = (float)i * inv255;

    // u0 = (x - mux)*s00 + dy*s10  -> hoist the row-constant part
    float t0[NK];
#pragma unroll
    for (int k = 0; k < NK; k++) t0[k] = (x - mux[k]) * A[k];

    const float NEG_HALF_LOG2E = -0.7213475204444817f;  // -0.5 * log2(e)

    float4 res;
    float* resv = &res.x;
#pragma unroll
    for (int v = 0; v < PIX_PER_THREAD; v++) {
        const float y = (float)(j0 + v) * inv255;
        float g   = 0.0f;
        float acc = 0.0f;
#pragma unroll
        for (int k = 0; k < NK; k++) {
            const float dy = y - muy[k];
            const float u0 = fmaf(dy, C[k], t0[k]);
            const float u1 = dy * D[k];
            const float s  = fmaf(u0, u0, u1 * u1);
            const float e  = fast_ex2(s * NEG_HALF_LOG2E);   // exp(-0.5*s)
            g   += e;
            acc  = fmaf(e, wk[k], acc);
        }
        float r = __fdividef(acc, fmaxf(g, 1e-7f));
        r = fminf(fmaxf(r, 0.0f), 1.0f);
        resv[v] = r;
    }

    // p0 is a multiple of 4 -> 16B-aligned float4 store
    *reinterpret_cast<float4*>(out + (size_t)b * PIX + p0) = res;
}

extern "C" void kernel_launch(void* const* d_in, const int* in_sizes, int n_in,
                              void* d_out, int out_size) {
    // Inputs in metadata order: height (int), width (int), params (128*1*28 f32).
    // Be robust: pick the input whose element count matches the params tensor.
    const float* params = nullptr;
    for (int idx = 0; idx < n_in; idx++) {
        if (in_sizes[idx] == NBATCH * NPAR) {
            params = (const float*)d_in[idx];
        }
    }
    if (!params) params = (const float*)d_in[n_in - 1];

    float* out = (float*)d_out;

    dim3 grid(PIX / PIX_PER_BLOCK, NBATCH);   // (64, 128) = 8192 blocks
    moe_gauss_kernel<<<grid, THREADS>>>(params, out);
}

// round 4
// speedup vs baseline: 1.0548x; 1.0548x over previous
#include <cuda_runtime.h>
#include <cuda_bf16.h>

// Problem constants (fixed by setup_inputs)
#define HEIGHT 256
#define WIDTH  256
#define NBATCH 128
#define NK     4
#define NPAR   28
#define PIX    (HEIGHT * WIDTH)
#define PPT    8                       // pixels per thread (4 packed pairs)
#define THREADS 256
#define PPB    (THREADS * PPT)         // 2048 pixels per block

typedef unsigned long long u64;

// ---- packed f32x2 helpers (sm_103a FFMA2 path, PTX-only) ----
__device__ __forceinline__ u64 pk2(float lo, float hi) {
    u64 r; asm("mov.b64 %0, {%1, %2};" : "=l"(r) : "f"(lo), "f"(hi)); return r;
}
__device__ __forceinline__ void upk2(u64 v, float& lo, float& hi) {
    asm("mov.b64 {%0, %1}, %2;" : "=f"(lo), "=f"(hi) : "l"(v));
}
__device__ __forceinline__ u64 fma2(u64 a, u64 b, u64 c) {
    u64 d; asm("fma.rn.f32x2 %0, %1, %2, %3;" : "=l"(d) : "l"(a), "l"(b), "l"(c)); return d;
}
__device__ __forceinline__ u64 mul2(u64 a, u64 b) {
    u64 d; asm("mul.rn.f32x2 %0, %1, %2;" : "=l"(d) : "l"(a), "l"(b)); return d;
}
__device__ __forceinline__ u64 add2(u64 a, u64 b) {
    u64 d; asm("add.rn.f32x2 %0, %1, %2;" : "=l"(d) : "l"(a), "l"(b)); return d;
}
__device__ __forceinline__ float fast_ex2(float x) {
    float r; asm("ex2.approx.f32 %0, %1;" : "=f"(r) : "f"(x)); return r;
}

__global__ __launch_bounds__(THREADS, 4)
void moe_gauss_kernel(const float* __restrict__ params, float* __restrict__ out) {
    const int b   = blockIdx.y;
    const int p0  = blockIdx.x * PPB + threadIdx.x * PPT;
    const int row = p0 >> 8;           // all 8 pixels share the same row (8 | 256)
    const int j0  = p0 & 255;

    const float* __restrict__ p = params + b * NPAR;

    // R = sqrt(0.5 * log2(e)); scaling Sigma by R folds the -0.5*log2e EX2
    // argument scale into the linear transform: exp(-0.5*s) = ex2(-(u0'^2+u1'^2)).
    const float R = 0.8493218002880191f;
    const float inv255 = 1.0f / 255.0f;
    const float x = (float)row * inv255;

    // Per-Gaussian packed constants: u0 = fma(y, C', b0), u1 = fma(y, D', b1)
    u64 C2[NK], D2[NK], B0[NK], B1[NK], W2[NK];
#pragma unroll
    for (int k = 0; k < NK; k++) {
        const float mux = __ldg(p + k);
        const float muy = __ldg(p + NK + k);
        const float wk  = __ldg(p + 2 * NK + k);
        const float A   = __ldg(p + 3 * NK + 4 * k + 0) * R;   // s00 * R
        const float C   = __ldg(p + 3 * NK + 4 * k + 2) * R;   // s10 * R
        const float D   = __ldg(p + 3 * NK + 4 * k + 3) * R;   // s11 * R
        const float t0  = (x - mux) * A;
        const float b0  = fmaf(-muy, C, t0);
        const float b1  = -muy * D;
        C2[k] = pk2(C, C);
        D2[k] = pk2(D, D);
        B0[k] = pk2(b0, b0);
        B1[k] = pk2(b1, b1);
        W2[k] = pk2(wk, wk);
    }

    float res[PPT];
#pragma unroll
    for (int q = 0; q < PPT / 2; q++) {
        const float ylo = (float)(j0 + 2 * q)     * inv255;
        const float yhi = (float)(j0 + 2 * q + 1) * inv255;
        const u64 y2 = pk2(ylo, yhi);

        u64 g2 = 0ull;   // packed {0.0f, 0.0f}
        u64 a2 = 0ull;
#pragma unroll
        for (int k = 0; k < NK; k++) {
            u64 u0 = fma2(y2, C2[k], B0[k]);
            u64 u1 = fma2(y2, D2[k], B1[k]);
            u64 t  = mul2(u1, u1);
            u64 s  = fma2(u0, u0, t);
            s ^= 0x8000000080000000ull;           // negate both halves (LOP)
            float slo, shi;
            upk2(s, slo, shi);
            const float elo = fast_ex2(slo);
            const float ehi = fast_ex2(shi);
            const u64 e2 = pk2(elo, ehi);
            g2 = add2(g2, e2);
            a2 = fma2(e2, W2[k], a2);
        }
        float glo, ghi, alo, ahi;
        upk2(g2, glo, ghi);
        upk2(a2, alo, ahi);
        res[2 * q]     = __saturatef(__fdividef(alo, fmaxf(glo, 1e-7f)));
        res[2 * q + 1] = __saturatef(__fdividef(ahi, fmaxf(ghi, 1e-7f)));
    }

    // p0 is a multiple of 8 -> two aligned float4 stores
    float* dst = out + (size_t)b * PIX + p0;
    *reinterpret_cast<float4*>(dst)     = make_float4(res[0], res[1], res[2], res[3]);
    *reinterpret_cast<float4*>(dst + 4) = make_float4(res[4], res[5], res[6], res[7]);
}

extern "C" void kernel_launch(void* const* d_in, const int* in_sizes, int n_in,
                              void* d_out, int out_size) {
    const float* params = nullptr;
    for (int idx = 0; idx < n_in; idx++) {
        if (in_sizes[idx] == NBATCH * NPAR) params = (const float*)d_in[idx];
    }
    if (!params) params = (const float*)d_in[n_in - 1];

    float* out = (float*)d_out;
    dim3 grid(PIX / PPB, NBATCH);      // (32, 128) = 4096 blocks
    moe_gauss_kernel<<<grid, THREADS>>>(params, out);
}

// round 8
// speedup vs baseline: 1.1216x; 1.0634x over previous
#include <cuda_runtime.h>
#include <cuda_bf16.h>

// Problem constants (fixed by setup_inputs)
#define HEIGHT 256
#define WIDTH  256
#define NBATCH 128
#define NK     4
#define NPAR   28
#define PIX    (HEIGHT * WIDTH)
#define PPT    16                      // pixels per thread (8 packed pairs)
#define THREADS 256
#define PPB    (THREADS * PPT)         // 4096 pixels per block

typedef unsigned long long u64;

// ---- packed f32x2 helpers (sm_103a FFMA2 path, PTX-only) ----
__device__ __forceinline__ u64 pk2(float lo, float hi) {
    u64 r; asm("mov.b64 %0, {%1, %2};" : "=l"(r) : "f"(lo), "f"(hi)); return r;
}
__device__ __forceinline__ void upk2(u64 v, float& lo, float& hi) {
    asm("mov.b64 {%0, %1}, %2;" : "=f"(lo), "=f"(hi) : "l"(v));
}
__device__ __forceinline__ u64 fma2(u64 a, u64 b, u64 c) {
    u64 d; asm("fma.rn.f32x2 %0, %1, %2, %3;" : "=l"(d) : "l"(a), "l"(b), "l"(c)); return d;
}
__device__ __forceinline__ u64 mul2(u64 a, u64 b) {
    u64 d; asm("mul.rn.f32x2 %0, %1, %2;" : "=l"(d) : "l"(a), "l"(b)); return d;
}
__device__ __forceinline__ u64 add2(u64 a, u64 b) {
    u64 d; asm("add.rn.f32x2 %0, %1, %2;" : "=l"(d) : "l"(a), "l"(b)); return d;
}
__device__ __forceinline__ float fast_ex2(float x) {
    float r; asm("ex2.approx.f32 %0, %1;" : "=f"(r) : "f"(x)); return r;
}

__global__ __launch_bounds__(THREADS, 3)
void moe_gauss_kernel(const float* __restrict__ params, float* __restrict__ out) {
    const int b   = blockIdx.y;
    const int p0  = blockIdx.x * PPB + threadIdx.x * PPT;
    const int row = p0 >> 8;           // all 16 pixels share the same row (16 | 256)
    const int j0  = p0 & 255;

    const float* __restrict__ p = params + b * NPAR;

    const float inv255 = 1.0f / 255.0f;
    const float x = (float)row * inv255;
    // exp(-0.5*s) = ex2(s * NEG_HALF_LOG2E); applied via one packed mul (fma pipe),
    // replacing the 64-bit XOR negate (2x LOP3 on the alu pipe).
    const float NEG_HALF_LOG2E = -0.7213475204444817f;

    // Per-Gaussian packed constants: u0 = fma(y, C, b0), u1 = fma(y, D, b1)
    u64 C2[NK], D2[NK], B0[NK], B1[NK], W2[NK];
#pragma unroll
    for (int k = 0; k < NK; k++) {
        const float mux = __ldg(p + k);
        const float muy = __ldg(p + NK + k);
        const float wk  = __ldg(p + 2 * NK + k);
        const float A   = __ldg(p + 3 * NK + 4 * k + 0);   // s00
        const float C   = __ldg(p + 3 * NK + 4 * k + 2);   // s10
        const float D   = __ldg(p + 3 * NK + 4 * k + 3);   // s11
        const float t0  = (x - mux) * A;
        const float b0  = fmaf(-muy, C, t0);
        const float b1  = -muy * D;
        C2[k] = pk2(C, C);
        D2[k] = pk2(D, D);
        B0[k] = pk2(b0, b0);
        B1[k] = pk2(b1, b1);
        W2[k] = pk2(wk, wk);
    }

    const u64 NH2 = pk2(NEG_HALF_LOG2E, NEG_HALF_LOG2E);
    const u64 DY2 = pk2(2.0f * inv255, 2.0f * inv255);
    u64 y2 = pk2((float)j0 * inv255, (float)(j0 + 1) * inv255);

    float res[PPT];
#pragma unroll
    for (int q = 0; q < PPT / 2; q++) {
        u64 g2 = 0ull;   // packed {0.0f, 0.0f}
        u64 a2 = 0ull;
#pragma unroll
        for (int k = 0; k < NK; k++) {
            u64 u0 = fma2(y2, C2[k], B0[k]);
            u64 u1 = fma2(y2, D2[k], B1[k]);
            u64 t  = mul2(u1, u1);
            u64 s  = fma2(u0, u0, t);
            u64 sm = mul2(s, NH2);                 // scale + negate, fma pipe
            float slo, shi;
            upk2(sm, slo, shi);
            const u64 e2 = pk2(fast_ex2(slo), fast_ex2(shi));
            g2 = add2(g2, e2);
            a2 = fma2(e2, W2[k], a2);
        }
        float glo, ghi, alo, ahi;
        upk2(g2, glo, ghi);
        upk2(a2, alo, ahi);
        res[2 * q]     = __saturatef(__fdividef(alo, fmaxf(glo, 1e-7f)));
        res[2 * q + 1] = __saturatef(__fdividef(ahi, fmaxf(ghi, 1e-7f)));
        y2 = add2(y2, DY2);                        // advance both columns by 2/255
    }

    // p0 is a multiple of 16 -> four aligned float4 stores
    float* dst = out + (size_t)b * PIX + p0;
#pragma unroll
    for (int v = 0; v < PPT / 4; v++) {
        *reinterpret_cast<float4*>(dst + 4 * v) =
            make_float4(res[4 * v], res[4 * v + 1], res[4 * v + 2], res[4 * v + 3]);
    }
}

extern "C" void kernel_launch(void* const* d_in, const int* in_sizes, int n_in,
                              void* d_out, int out_size) {
    const float* params = nullptr;
    for (int idx = 0; idx < n_in; idx++) {
        if (in_sizes[idx] == NBATCH * NPAR) params = (const float*)d_in[idx];
    }
    if (!params) params = (const float*)d_in[n_in - 1];

    float* out = (float*)d_out;
    dim3 grid(PIX / PPB, NBATCH);      // (16, 128) = 2048 blocks
    moe_gauss_kernel<<<grid, THREADS>>>(params, out);
}

// round 10
// speedup vs baseline: 1.2452x; 1.1103x over previous
#include <cuda_runtime.h>
#include <cuda_bf16.h>

// Problem constants (fixed by setup_inputs)
#define HEIGHT 256
#define WIDTH  256
#define NBATCH 128
#define NK     4
#define NPAR   28
#define PIX    (HEIGHT * WIDTH)
#define PPT    16                      // pixels per thread (8 packed pairs)
#define THREADS 256
#define PPB    (THREADS * PPT)         // 4096 pixels per block

typedef unsigned long long u64;

// ---- packed f32x2 helpers (sm_103a FFMA2 path, PTX-only) ----
__device__ __forceinline__ u64 pk2(float lo, float hi) {
    u64 r; asm("mov.b64 %0, {%1, %2};" : "=l"(r) : "f"(lo), "f"(hi)); return r;
}
__device__ __forceinline__ void upk2(u64 v, float& lo, float& hi) {
    asm("mov.b64 {%0, %1}, %2;" : "=f"(lo), "=f"(hi) : "l"(v));
}
__device__ __forceinline__ u64 fma2(u64 a, u64 b, u64 c) {
    u64 d; asm("fma.rn.f32x2 %0, %1, %2, %3;" : "=l"(d) : "l"(a), "l"(b), "l"(c)); return d;
}
__device__ __forceinline__ u64 add2(u64 a, u64 b) {
    u64 d; asm("add.rn.f32x2 %0, %1, %2;" : "=l"(d) : "l"(a), "l"(b)); return d;
}
__device__ __forceinline__ float fast_ex2(float x) {
    float r; asm("ex2.approx.f32 %0, %1;" : "=f"(r) : "f"(x)); return r;
}

__global__ __launch_bounds__(THREADS, 4)
void moe_gauss_kernel(const float* __restrict__ params, float* __restrict__ out) {
    const int b   = blockIdx.y;
    const int p0  = blockIdx.x * PPB + threadIdx.x * PPT;
    const int row = p0 >> 8;           // all 16 pixels share the same row (16 | 256)
    const int j0  = p0 & 255;

    const float* __restrict__ p = params + b * NPAR;

    const float inv255 = 1.0f / 255.0f;
    const float x = (float)row * inv255;
    const float h = 0.7213475204444817f;   // 0.5 * log2(e)

    // Quadratic-in-y expansion of the exponent, per Gaussian:
    //   u0 = C*y + b0,  u1 = D*y + b1   (b0,b1 fold in x and mu)
    //   ex2 argument = -h*(u0^2+u1^2) = al*y^2 + be*y + ga
    // Inner loop: 2 packed FMA (Horner) + 2 EX2 + 2 packed accum per Gaussian.
    u64 AL2[NK], BE2[NK], GA2[NK], W2[NK];
#pragma unroll
    for (int k = 0; k < NK; k++) {
        const float mux = __ldg(p + k);
        const float muy = __ldg(p + NK + k);
        const float wk  = __ldg(p + 2 * NK + k);
        const float A   = __ldg(p + 3 * NK + 4 * k + 0);   // s00
        const float C   = __ldg(p + 3 * NK + 4 * k + 2);   // s10
        const float D   = __ldg(p + 3 * NK + 4 * k + 3);   // s11

        const float t   = x - mux;
        const float b0  = fmaf(t, A, -muy * C);
        const float b1  = -muy * D;
        const float al  = -h * fmaf(C, C, D * D);
        const float be  = -2.0f * h * fmaf(C, b0, D * b1);
        const float ga  = -h * fmaf(b0, b0, b1 * b1);

        AL2[k] = pk2(al, al);
        BE2[k] = pk2(be, be);
        GA2[k] = pk2(ga, ga);
        W2[k]  = pk2(wk, wk);
    }

    const u64 DY2 = pk2(2.0f * inv255, 2.0f * inv255);
    u64 y2 = pk2((float)j0 * inv255, (float)(j0 + 1) * inv255);

    float* dst = out + (size_t)b * PIX + p0;

#pragma unroll
    for (int v = 0; v < PPT / 4; v++) {
        float4 r4;
        float* rp = &r4.x;
#pragma unroll
        for (int q = 0; q < 2; q++) {
            u64 g2 = 0ull;   // packed {0.0f, 0.0f}
            u64 a2 = 0ull;
#pragma unroll
            for (int k = 0; k < NK; k++) {
                const u64 s = fma2(y2, fma2(y2, AL2[k], BE2[k]), GA2[k]);
                float slo, shi;
                upk2(s, slo, shi);
                const u64 e2 = pk2(fast_ex2(slo), fast_ex2(shi));
                g2 = add2(g2, e2);
                a2 = fma2(e2, W2[k], a2);
            }
            float glo, ghi, alo, ahi;
            upk2(g2, glo, ghi);
            upk2(a2, alo, ahi);
            rp[2 * q]     = __saturatef(__fdividef(alo, fmaxf(glo, 1e-7f)));
            rp[2 * q + 1] = __saturatef(__fdividef(ahi, fmaxf(ghi, 1e-7f)));
            y2 = add2(y2, DY2);        // advance both columns by 2/255
        }
        // p0 is a multiple of 16 -> aligned float4 store, issued as soon as ready
        *reinterpret_cast<float4*>(dst + 4 * v) = r4;
    }
}

extern "C" void kernel_launch(void* const* d_in, const int* in_sizes, int n_in,
                              void* d_out, int out_size) {
    const float* params = nullptr;
    for (int idx = 0; idx < n_in; idx++) {
        if (in_sizes[idx] == NBATCH * NPAR) params = (const float*)d_in[idx];
    }
    if (!params) params = (const float*)d_in[n_in - 1];

    float* out = (float*)d_out;
    dim3 grid(PIX / PPB, NBATCH);      // (16, 128) = 2048 blocks
    moe_gauss_kernel<<<grid, THREADS>>>(params, out);
}